// round 8
// baseline (speedup 1.0000x reference)
#include <cuda_runtime.h>
#include <cuda_bf16.h>
#include <math.h>

// VGAE decoder = 3-layer GCN. layer(h,W,b) = A(hW)+b ; A(hW)=(Ah)W so layer1
// aggregates in the 64-dim input space. Atomic-free gathers via per-launch CSC.
// R8: R6/R7 plan, GEMM tile height via macro (no constexpr-fn; nvcc here has
// no --expt-relaxed-constexpr).

#define NMAX 100000
#define EMAX 1600000
#define SCAN_B 1024

// rows-per-block for GEMM so that (K*M + BR*K)*4 <= 48KB, BR in {32,64}
#define GEMM_BR(K, M) ((((K) * (M) + 64 * (K)) * 4 <= 49152) ? 64 : 32)

// ---------------- device scratch -------------------------------------------
__device__ unsigned long long g_pack[NMAX];   // (cnt<<44) | fixedpoint(deg sum)
__device__ float g_dinv[NMAX];
__device__ int   g_cnt[NMAX];
__device__ int   g_off[NMAX];
__device__ int   g_cur[NMAX];
__device__ int   g_bsum[128];
__device__ int   g_bpre[128];
__device__ __align__(8)  int2  g_edge[EMAX];          // packed {src, wn-bits}
__device__ __align__(16) float g_bufA[(size_t)NMAX * 128];
__device__ __align__(16) float g_bufB[(size_t)NMAX * 128];

template<int SEL>
__device__ __forceinline__ const float* sel_src(const float* p) {
    if (SEL == 1) return g_bufA;
    if (SEL == 2) return g_bufB;
    return p;
}
template<int SEL>
__device__ __forceinline__ float* sel_dst(float* p) {
    if (SEL == 1) return g_bufA;
    if (SEL == 2) return g_bufB;
    return p;
}

// ---------------- preprocessing --------------------------------------------
__global__ void init_nodes(int n) {
    int i = blockIdx.x * blockDim.x + threadIdx.x;
    if (i < n) g_pack[i] = 0ull;
}

__device__ __forceinline__ void deg_add(int c, float w, int n) {
    if ((unsigned)c >= (unsigned)n) return;   // guard
    unsigned long long v = (1ull << 44) |
        (unsigned long long)(unsigned)__float2uint_rn(w * 1048576.0f);
    atomicAdd(&g_pack[c], v);
}

__global__ void edge_deg(const int* __restrict__ ei,
                         const float* __restrict__ ew, int E, int n, int vec) {
    int e0 = (blockIdx.x * blockDim.x + threadIdx.x) * 4;
    if (e0 >= E) return;
    if (vec && e0 + 4 <= E) {
        int4   c4 = *(const int4*)(ei + E + e0);
        float4 w4 = *(const float4*)(ew + e0);
        deg_add(c4.x, w4.x, n);
        deg_add(c4.y, w4.y, n);
        deg_add(c4.z, w4.z, n);
        deg_add(c4.w, w4.w, n);
    } else {
        for (int e = e0; e < E && e < e0 + 4; e++)
            deg_add(ei[E + e], ew[e], n);
    }
}

__global__ void node_dinv(int n) {
    int i = blockIdx.x * blockDim.x + threadIdx.x;
    if (i >= n) return;
    unsigned long long p = g_pack[i];
    int cnt = (int)(p >> 44);
    float deg = 1.0f + (float)(p & ((1ull << 44) - 1)) * (1.0f / 1048576.0f);
    g_dinv[i] = rsqrtf(deg);
    g_cnt[i]  = cnt;
}

// exclusive scan of g_cnt -> g_off
__global__ void scan_blocks(int n) {
    __shared__ int s[SCAN_B];
    int t = threadIdx.x;
    int i = blockIdx.x * SCAN_B + t;
    int v = (i < n) ? g_cnt[i] : 0;
    s[t] = v;
    __syncthreads();
    for (int o = 1; o < SCAN_B; o <<= 1) {
        int x = (t >= o) ? s[t - o] : 0;
        __syncthreads();
        s[t] += x;
        __syncthreads();
    }
    if (i < n) g_off[i] = s[t] - v;
    if (t == SCAN_B - 1) g_bsum[blockIdx.x] = s[t];
}

__global__ void scan_sums(int nb) {
    __shared__ int s[128];
    int t = threadIdx.x;
    int v = (t < nb) ? g_bsum[t] : 0;
    s[t] = v;
    __syncthreads();
    for (int o = 1; o < 128; o <<= 1) {
        int x = (t >= o) ? s[t - o] : 0;
        __syncthreads();
        s[t] += x;
        __syncthreads();
    }
    if (t < nb) g_bpre[t] = s[t] - v;
}

__global__ void scan_add(int n) {
    int i = blockIdx.x * blockDim.x + threadIdx.x;
    if (i < n) {
        int o = g_off[i] + g_bpre[i >> 10];
        g_off[i] = o;
        g_cur[i] = o;
    }
}

__device__ __forceinline__ void scat1(int r, int c, float w, int n) {
    if ((unsigned)r >= (unsigned)n || (unsigned)c >= (unsigned)n) return;  // guard
    float wn = g_dinv[r] * w * g_dinv[c];
    int p = atomicAdd(&g_cur[c], 1);
    g_edge[p] = make_int2(r, __float_as_int(wn));
}

__global__ void edge_scatter(const int* __restrict__ ei,
                             const float* __restrict__ ew, int E, int n, int vec) {
    int e0 = (blockIdx.x * blockDim.x + threadIdx.x) * 4;
    if (e0 >= E) return;
    if (vec && e0 + 4 <= E) {
        int4   r4 = *(const int4*)(ei + e0);
        int4   c4 = *(const int4*)(ei + E + e0);
        float4 w4 = *(const float4*)(ew + e0);
        scat1(r4.x, c4.x, w4.x, n);
        scat1(r4.y, c4.y, w4.y, n);
        scat1(r4.z, c4.z, w4.z, n);
        scat1(r4.w, c4.w, w4.w, n);
    } else {
        for (int e = e0; e < E && e < e0 + 4; e++)
            scat1(ei[e], ei[E + e], ew[e], n);
    }
}

// ---------------- gather: out[n] = sum_e wn*T[src] + dinv^2*T[n] (+b)(sig) --
template<int M, int SSEL, int DSEL, bool BIAS, bool SIG>
__global__ void __launch_bounds__(256)
gather4_kernel(const float* __restrict__ Tp,
               const float* __restrict__ bias,
               float* __restrict__ outp, int n) {
    constexpr int L = M / 4;
    const float4* T = (const float4*)sel_src<SSEL>(Tp);
    float4* out = (float4*)sel_dst<DSEL>(outp);
    int node = blockIdx.x * (256 / L) + threadIdx.y;
    if (node >= n) return;
    int m = threadIdx.x;
    int start = g_off[node];
    int cnt   = g_cnt[node];

    float ax = 0.f, ay = 0.f, az = 0.f, aw = 0.f;
    int i = 0;
    for (; i + 4 <= cnt; i += 4) {
        int2 e0 = g_edge[start + i];
        int2 e1 = g_edge[start + i + 1];
        int2 e2 = g_edge[start + i + 2];
        int2 e3 = g_edge[start + i + 3];
        float4 t0 = T[(size_t)e0.x * L + m];
        float4 t1 = T[(size_t)e1.x * L + m];
        float4 t2 = T[(size_t)e2.x * L + m];
        float4 t3 = T[(size_t)e3.x * L + m];
        float w0 = __int_as_float(e0.y), w1 = __int_as_float(e1.y);
        float w2 = __int_as_float(e2.y), w3 = __int_as_float(e3.y);
        ax += w0 * t0.x; ay += w0 * t0.y; az += w0 * t0.z; aw += w0 * t0.w;
        ax += w1 * t1.x; ay += w1 * t1.y; az += w1 * t1.z; aw += w1 * t1.w;
        ax += w2 * t2.x; ay += w2 * t2.y; az += w2 * t2.z; aw += w2 * t2.w;
        ax += w3 * t3.x; ay += w3 * t3.y; az += w3 * t3.z; aw += w3 * t3.w;
    }
    for (; i < cnt; i++) {
        int2 e0 = g_edge[start + i];
        float4 t0 = T[(size_t)e0.x * L + m];
        float w0 = __int_as_float(e0.y);
        ax += w0 * t0.x; ay += w0 * t0.y; az += w0 * t0.z; aw += w0 * t0.w;
    }
    float di = g_dinv[node];
    float ns = di * di;
    float4 ts = T[(size_t)node * L + m];
    ax += ns * ts.x; ay += ns * ts.y; az += ns * ts.z; aw += ns * ts.w;
    if (BIAS) {
        float4 bb = ((const float4*)bias)[m];
        ax += bb.x; ay += bb.y; az += bb.z; aw += bb.w;
    }
    if (SIG) {
        ax = 1.0f / (1.0f + __expf(-ax));
        ay = 1.0f / (1.0f + __expf(-ay));
        az = 1.0f / (1.0f + __expf(-az));
        aw = 1.0f / (1.0f + __expf(-aw));
    }
    out[(size_t)node * L + m] = make_float4(ax, ay, az, aw);
}

// ---------------- single-stage GEMM: out[N,M] = A[N,K] @ W[K,M] (+b) -------
// A strip (BR x K) + full W (K x M) in smem; one sync; full-K FMA loop.
// BR sized (macro) so smem <= 48KB.
template<int K, int M, int SSEL, int DSEL, bool BIAS>
__global__ void __launch_bounds__(256)
gemm_kernel(const float* __restrict__ Ap, const float* __restrict__ W,
            const float* __restrict__ bias, float* __restrict__ outp, int n) {
    const float* A = sel_src<SSEL>(Ap);
    float* out = sel_dst<DSEL>(outp);
    constexpr int BR  = GEMM_BR(K, M);
    constexpr int TX  = M / 4;
    constexpr int TY  = 256 / TX;
    constexpr int RPT = BR / TY;          // rows per thread
    static_assert(RPT >= 1, "tile config");
    __shared__ float sW[K * M];
    __shared__ float sA[BR * K];
    int tx = threadIdx.x, ty = threadIdx.y;
    int tid = ty * TX + tx;

    for (int i = tid; i < K * M / 4; i += 256)
        ((float4*)sW)[i] = ((const float4*)W)[i];

    int row0 = blockIdx.x * BR;
    const float4* A4 = (const float4*)(A + (size_t)row0 * K);
    constexpr int TOT4 = BR * K / 4;
    if (row0 + BR <= n) {
        for (int i = tid; i < TOT4; i += 256) ((float4*)sA)[i] = A4[i];
    } else {
        for (int i = tid; i < TOT4; i += 256) {
            int r = i / (K / 4);
            ((float4*)sA)[i] = (row0 + r < n) ? A4[i] : make_float4(0.f, 0.f, 0.f, 0.f);
        }
    }
    __syncthreads();

    float acc[RPT][4];
#pragma unroll
    for (int r = 0; r < RPT; r++)
#pragma unroll
        for (int c = 0; c < 4; c++) acc[r][c] = 0.0f;

#pragma unroll 4
    for (int k = 0; k < K; k++) {
        float4 b4 = *(const float4*)&sW[k * M + tx * 4];
#pragma unroll
        for (int r = 0; r < RPT; r++) {
            float a = sA[(ty * RPT + r) * K + k];
            acc[r][0] += a * b4.x;
            acc[r][1] += a * b4.y;
            acc[r][2] += a * b4.z;
            acc[r][3] += a * b4.w;
        }
    }

    float4 bb = make_float4(0.f, 0.f, 0.f, 0.f);
    if (BIAS) bb = *(const float4*)&bias[tx * 4];
#pragma unroll
    for (int r = 0; r < RPT; r++) {
        int gr = row0 + ty * RPT + r;
        if (gr < n) {
            float4 v;
            v.x = acc[r][0] + bb.x;
            v.y = acc[r][1] + bb.y;
            v.z = acc[r][2] + bb.z;
            v.w = acc[r][3] + bb.w;
            *(float4*)&out[(size_t)gr * M + tx * 4] = v;
        }
    }
}

// ---------------- launch ----------------------------------------------------
extern "C" void kernel_launch(void* const* d_in, const int* in_sizes, int n_in,
                              void* d_out, int out_size) {
    const float* x  = (const float*)d_in[0];
    const int*   ei = (const int*)d_in[1];
    const float* ew = (const float*)d_in[2];
    const float* W1 = (const float*)d_in[3];
    const float* b1 = (const float*)d_in[4];
    const float* W2 = (const float*)d_in[5];
    const float* b2 = (const float*)d_in[6];
    const float* W3 = (const float*)d_in[7];
    const float* b3 = (const float*)d_in[8];
    float* out = (float*)d_out;

    int N = in_sizes[0] / 64;
    int E = in_sizes[1] / 2;
    int vec = (E % 4 == 0) ? 1 : 0;

    int nb256_n = (N + 255) / 256;
    int nbe4    = (E / 4 + 256) / 256;   // each thread covers 4 edges
    int nbscan  = (N + SCAN_B - 1) / SCAN_B;

    init_nodes<<<nb256_n, 256>>>(N);
    edge_deg<<<nbe4, 256>>>(ei, ew, E, N, vec);
    node_dinv<<<nb256_n, 256>>>(N);
    scan_blocks<<<nbscan, SCAN_B>>>(N);
    scan_sums<<<1, 128>>>(nbscan);
    scan_add<<<nb256_n, 256>>>(N);
    edge_scatter<<<nbe4, 256>>>(ei, ew, E, N, vec);

    const int BR1 = GEMM_BR(64, 128);
    const int BR2 = GEMM_BR(128, 64);
    const int BR3 = GEMM_BR(64, 32);

    // layer 1 (aggregate-first): G = A x -> bufA ; H1 = G@W1+b1 -> bufB
    gather4_kernel<64, 0, 1, false, false><<<(N + 15) / 16, dim3(16, 16)>>>(x, nullptr, nullptr, N);
    gemm_kernel<64, 128, 1, 2, true><<<(N + BR1 - 1) / BR1, dim3(32, 8)>>>(nullptr, W1, b1, nullptr, N);

    // layer 2: T2 = H1@W2 -> bufA ; H2 = A T2 + b2 -> bufB
    gemm_kernel<128, 64, 2, 1, false><<<(N + BR2 - 1) / BR2, dim3(16, 16)>>>(nullptr, W2, nullptr, nullptr, N);
    gather4_kernel<64, 1, 2, true, false><<<(N + 15) / 16, dim3(16, 16)>>>(nullptr, b2, nullptr, N);

    // layer 3: T3 = H2@W3 -> bufA ; out = sigmoid(A T3 + b3)
    gemm_kernel<64, 32, 2, 1, false><<<(N + BR3 - 1) / BR3, dim3(8, 32)>>>(nullptr, W3, nullptr, nullptr, N);
    gather4_kernel<32, 1, 0, true, true><<<(N + 31) / 32, dim3(8, 32)>>>(nullptr, b3, out, N);

    (void)n_in; (void)out_size;
}

// round 10
// speedup vs baseline: 1.5178x; 1.5178x over previous
#include <cuda_runtime.h>
#include <cuda_bf16.h>
#include <math.h>

// VGAE decoder = 3-layer GCN. layer(h,W,b) = A(hW)+b ; A(hW)=(Ah)W.
// R10 (= R9 resubmit after infra failure): algebraic fusion.
//   h2 = A[(Ax)(W1W2)] + a*(b1W2) + b2, a = A.1 (row sums of A).
// Pipeline: gather1(x)->G (+writes a) ; G@W12 ; gather2(+a*bv+b2) ; @W3 ;
// gather3(+b3, sigmoid). Preprocessing/gather/GEMM all in known-good R5 form.

#define NMAX 100000
#define EMAX 1600000
#define SCAN_B 1024

// ---------------- device scratch -------------------------------------------
__device__ float g_deg[NMAX];
__device__ float g_dinv[NMAX];
__device__ float g_a[NMAX];                 // row sums of A
__device__ int   g_cnt[NMAX];
__device__ int   g_off[NMAX];
__device__ int   g_cur[NMAX];
__device__ int   g_bsum[128];
__device__ int   g_bpre[128];
__device__ __align__(8)  int2  g_edge[EMAX];  // packed {src, wn-bits}
__device__ __align__(16) float g_W12[64 * 64];
__device__ __align__(16) float g_bv[64];
__device__ __align__(16) float g_bufA[(size_t)NMAX * 64];
__device__ __align__(16) float g_bufB[(size_t)NMAX * 64];

template<int SEL>
__device__ __forceinline__ const float* sel_src(const float* p) {
    if (SEL == 1) return g_bufA;
    if (SEL == 2) return g_bufB;
    return p;
}
template<int SEL>
__device__ __forceinline__ float* sel_dst(float* p) {
    if (SEL == 1) return g_bufA;
    if (SEL == 2) return g_bufB;
    return p;
}
template<int SEL>
__device__ __forceinline__ const float* sel_w(const float* p) {
    if (SEL == 1) return g_W12;
    return p;
}

// ---------------- preprocessing (R5 form) -----------------------------------
__global__ void init_nodes(int n) {
    int i = blockIdx.x * blockDim.x + threadIdx.x;
    if (i < n) { g_deg[i] = 1.0f; g_cnt[i] = 0; }
}

__global__ void edge_deg(const int* __restrict__ ei,
                         const float* __restrict__ ew, int E, int n) {
    int e = blockIdx.x * blockDim.x + threadIdx.x;
    if (e >= E) return;
    int c = ei[E + e];
    if ((unsigned)c >= (unsigned)n) return;   // guard
    atomicAdd(&g_deg[c], ew[e]);
    atomicAdd(&g_cnt[c], 1);
}

__global__ void node_dinv(int n) {
    int i = blockIdx.x * blockDim.x + threadIdx.x;
    if (i < n) g_dinv[i] = rsqrtf(g_deg[i]);
}

__global__ void scan_blocks(int n) {
    __shared__ int s[SCAN_B];
    int t = threadIdx.x;
    int i = blockIdx.x * SCAN_B + t;
    int v = (i < n) ? g_cnt[i] : 0;
    s[t] = v;
    __syncthreads();
    for (int o = 1; o < SCAN_B; o <<= 1) {
        int x = (t >= o) ? s[t - o] : 0;
        __syncthreads();
        s[t] += x;
        __syncthreads();
    }
    if (i < n) g_off[i] = s[t] - v;
    if (t == SCAN_B - 1) g_bsum[blockIdx.x] = s[t];
}

__global__ void scan_sums(int nb) {
    __shared__ int s[128];
    int t = threadIdx.x;
    int v = (t < nb) ? g_bsum[t] : 0;
    s[t] = v;
    __syncthreads();
    for (int o = 1; o < 128; o <<= 1) {
        int x = (t >= o) ? s[t - o] : 0;
        __syncthreads();
        s[t] += x;
        __syncthreads();
    }
    if (t < nb) g_bpre[t] = s[t] - v;
}

__global__ void scan_add(int n) {
    int i = blockIdx.x * blockDim.x + threadIdx.x;
    if (i < n) {
        int o = g_off[i] + g_bpre[i >> 10];
        g_off[i] = o;
        g_cur[i] = o;
    }
}

__global__ void edge_scatter(const int* __restrict__ ei,
                             const float* __restrict__ ew, int E, int n) {
    int e = blockIdx.x * blockDim.x + threadIdx.x;
    if (e >= E) return;
    int r = ei[e];
    int c = ei[E + e];
    if ((unsigned)r >= (unsigned)n || (unsigned)c >= (unsigned)n) return;  // guard
    float wn = g_dinv[r] * ew[e] * g_dinv[c];
    int p = atomicAdd(&g_cur[c], 1);
    g_edge[p] = make_int2(r, __float_as_int(wn));
}

// ---------------- weight fusion: W12 = W1@W2, bv = b1@W2 --------------------
// W1: [64,128], W2: [128,64]. Blocks 0..15 -> W12 (4096 elems), block 16 -> bv.
__global__ void fuse_w(const float* __restrict__ W1, const float* __restrict__ W2,
                       const float* __restrict__ b1) {
    int t = blockIdx.x * 256 + threadIdx.x;
    if (t < 4096) {
        int i = t >> 6, j = t & 63;
        float s = 0.f;
#pragma unroll 8
        for (int k = 0; k < 128; k++)
            s += W1[i * 128 + k] * W2[k * 64 + j];
        g_W12[t] = s;
    } else if (t < 4096 + 64) {
        int j = t - 4096;
        float s = 0.f;
#pragma unroll 8
        for (int k = 0; k < 128; k++)
            s += b1[k] * W2[k * 64 + j];
        g_bv[j] = s;
    }
}

// ---------------- gather: out = A*T (+bias modes) ---------------------------
// BMODE: 0 none, 1 +bias[m], 2 +a[node]*bv[m]+bias[m]
template<int M, int SSEL, int DSEL, int BMODE, bool SIG, bool WRITEA>
__global__ void __launch_bounds__(256)
gather4_kernel(const float* __restrict__ Tp,
               const float* __restrict__ bias,
               float* __restrict__ outp, int n) {
    constexpr int L = M / 4;
    const float4* T = (const float4*)sel_src<SSEL>(Tp);
    float4* out = (float4*)sel_dst<DSEL>(outp);
    int node = blockIdx.x * (256 / L) + threadIdx.y;
    if (node >= n) return;
    int m = threadIdx.x;
    int start = g_off[node];
    int cnt   = g_cnt[node];

    float ax = 0.f, ay = 0.f, az = 0.f, aw = 0.f;
    float wsum = 0.f;
    int i = 0;
    for (; i + 4 <= cnt; i += 4) {
        int2 e0 = g_edge[start + i];
        int2 e1 = g_edge[start + i + 1];
        int2 e2 = g_edge[start + i + 2];
        int2 e3 = g_edge[start + i + 3];
        float4 t0 = T[(size_t)e0.x * L + m];
        float4 t1 = T[(size_t)e1.x * L + m];
        float4 t2 = T[(size_t)e2.x * L + m];
        float4 t3 = T[(size_t)e3.x * L + m];
        float w0 = __int_as_float(e0.y), w1 = __int_as_float(e1.y);
        float w2 = __int_as_float(e2.y), w3 = __int_as_float(e3.y);
        if (WRITEA) wsum += (w0 + w1) + (w2 + w3);
        ax += w0 * t0.x; ay += w0 * t0.y; az += w0 * t0.z; aw += w0 * t0.w;
        ax += w1 * t1.x; ay += w1 * t1.y; az += w1 * t1.z; aw += w1 * t1.w;
        ax += w2 * t2.x; ay += w2 * t2.y; az += w2 * t2.z; aw += w2 * t2.w;
        ax += w3 * t3.x; ay += w3 * t3.y; az += w3 * t3.z; aw += w3 * t3.w;
    }
    for (; i < cnt; i++) {
        int2 e0 = g_edge[start + i];
        float4 t0 = T[(size_t)e0.x * L + m];
        float w0 = __int_as_float(e0.y);
        if (WRITEA) wsum += w0;
        ax += w0 * t0.x; ay += w0 * t0.y; az += w0 * t0.z; aw += w0 * t0.w;
    }
    float di = g_dinv[node];
    float ns = di * di;
    float4 ts = T[(size_t)node * L + m];
    ax += ns * ts.x; ay += ns * ts.y; az += ns * ts.z; aw += ns * ts.w;
    if (WRITEA && m == 0) g_a[node] = wsum + ns;
    if (BMODE == 1) {
        float4 bb = ((const float4*)bias)[m];
        ax += bb.x; ay += bb.y; az += bb.z; aw += bb.w;
    } else if (BMODE == 2) {
        float an = g_a[node];
        float4 bv = ((const float4*)g_bv)[m];
        float4 bb = ((const float4*)bias)[m];
        ax += an * bv.x + bb.x; ay += an * bv.y + bb.y;
        az += an * bv.z + bb.z; aw += an * bv.w + bb.w;
    }
    if (SIG) {
        ax = 1.0f / (1.0f + __expf(-ax));
        ay = 1.0f / (1.0f + __expf(-ay));
        az = 1.0f / (1.0f + __expf(-az));
        aw = 1.0f / (1.0f + __expf(-aw));
    }
    out[(size_t)node * L + m] = make_float4(ax, ay, az, aw);
}

// ---------------- GEMM (R5 two-stage form): out[N,M] = A[N,K] @ W[K,M] -----
template<int K, int M, int SSEL, int DSEL, int WSEL>
__global__ void __launch_bounds__(256)
gemm_kernel(const float* __restrict__ Ap, const float* __restrict__ Wp,
            float* __restrict__ outp, int n) {
    const float* A = sel_src<SSEL>(Ap);
    const float* W = sel_w<WSEL>(Wp);
    float* out = sel_dst<DSEL>(outp);
    constexpr int BR = 64, KC = 32;
    constexpr int TX = M / 4, TY = 8;
    __shared__ float sW[K * M];
    __shared__ float sA[BR * KC];   // [r][k], stride KC
    int tx = threadIdx.x, ty = threadIdx.y;
    int tid = ty * TX + tx;
    constexpr int NTH = TX * TY;
    for (int i = tid; i < K * M; i += NTH) sW[i] = W[i];

    int row0 = blockIdx.x * BR;
    float acc[8][4];
#pragma unroll
    for (int r = 0; r < 8; r++)
#pragma unroll
        for (int c = 0; c < 4; c++) acc[r][c] = 0.0f;

    for (int kc = 0; kc < K; kc += KC) {
        __syncthreads();
        for (int i = tid; i < BR * KC; i += NTH) {
            int r = i / KC, k = i % KC;
            int gr = row0 + r;
            sA[i] = (gr < n) ? A[(size_t)gr * K + kc + k] : 0.0f;
        }
        __syncthreads();
#pragma unroll
        for (int k = 0; k < KC; k++) {
            float4 b4 = *(const float4*)&sW[(kc + k) * M + tx * 4];
#pragma unroll
            for (int r = 0; r < 8; r++) {
                float a = sA[(ty * 8 + r) * KC + k];
                acc[r][0] += a * b4.x;
                acc[r][1] += a * b4.y;
                acc[r][2] += a * b4.z;
                acc[r][3] += a * b4.w;
            }
        }
    }

#pragma unroll
    for (int r = 0; r < 8; r++) {
        int gr = row0 + ty * 8 + r;
        if (gr < n) {
            float4 v = make_float4(acc[r][0], acc[r][1], acc[r][2], acc[r][3]);
            *(float4*)&out[(size_t)gr * M + tx * 4] = v;
        }
    }
}

// ---------------- launch ----------------------------------------------------
extern "C" void kernel_launch(void* const* d_in, const int* in_sizes, int n_in,
                              void* d_out, int out_size) {
    const float* x  = (const float*)d_in[0];
    const int*   ei = (const int*)d_in[1];
    const float* ew = (const float*)d_in[2];
    const float* W1 = (const float*)d_in[3];
    const float* b1 = (const float*)d_in[4];
    const float* W2 = (const float*)d_in[5];
    const float* b2 = (const float*)d_in[6];
    const float* W3 = (const float*)d_in[7];
    const float* b3 = (const float*)d_in[8];
    float* out = (float*)d_out;

    int N = in_sizes[0] / 64;
    int E = in_sizes[1] / 2;

    int nb256_n = (N + 255) / 256;
    int nb256_e = (E + 255) / 256;
    int nbscan  = (N + SCAN_B - 1) / SCAN_B;

    // preprocessing + weight fusion (fuse_w overlaps edge preprocessing)
    init_nodes<<<nb256_n, 256>>>(N);
    fuse_w<<<17, 256>>>(W1, W2, b1);
    edge_deg<<<nb256_e, 256>>>(ei, ew, E, N);
    node_dinv<<<nb256_n, 256>>>(N);
    scan_blocks<<<nbscan, SCAN_B>>>(N);
    scan_sums<<<1, 128>>>(nbscan);
    scan_add<<<nb256_n, 256>>>(N);
    edge_scatter<<<nb256_e, 256>>>(ei, ew, E, N);

    // G = A x -> bufA (also writes g_a)
    gather4_kernel<64, 0, 1, 0, false, true><<<(N + 15) / 16, dim3(16, 16)>>>(x, nullptr, nullptr, N);
    // T2 = G @ W12 -> bufB
    gemm_kernel<64, 64, 1, 2, 1><<<(N + 63) / 64, dim3(16, 8)>>>(nullptr, nullptr, nullptr, N);
    // H2 = A T2 + a*bv + b2 -> bufA
    gather4_kernel<64, 2, 1, 2, false, false><<<(N + 15) / 16, dim3(16, 16)>>>(nullptr, b2, nullptr, N);
    // T3 = H2 @ W3 -> bufB
    gemm_kernel<64, 32, 1, 2, 0><<<(N + 63) / 64, dim3(8, 8)>>>(nullptr, W3, nullptr, N);
    // out = sigmoid(A T3 + b3)
    gather4_kernel<32, 2, 0, 1, true, false><<<(N + 31) / 32, dim3(8, 32)>>>(nullptr, b3, out, N);

    (void)n_in; (void)out_size;
}

// round 11
// speedup vs baseline: 1.8407x; 1.2128x over previous
#include <cuda_runtime.h>
#include <cuda_bf16.h>
#include <math.h>

// VGAE decoder = 3-layer GCN, fully linearized:
//   G = A x ; a = A.1 ; V = G @ (W1W2W3) ; P = A V ; a2 = A a ;
//   out = sigmoid(A P + a2*c + a*d + b3),  c = b1W2W3, d = b2W3.
// One 64->32 GEMM, gathers at 64/32/32 dims. CSC built per launch.

#define NMAX 100000
#define EMAX 1600000
#define SCAN_B 1024

// ---------------- device scratch -------------------------------------------
__device__ float g_deg[NMAX];
__device__ float g_dinv[NMAX];
__device__ float g_a[NMAX];                 // A.1
__device__ float g_a2[NMAX];                // A.(A.1)
__device__ int   g_cnt[NMAX];
__device__ int   g_off[NMAX];
__device__ int   g_cur[NMAX];
__device__ int   g_bsum[128];
__device__ int   g_bpre[128];
__device__ __align__(8)  int2  g_edge[EMAX];  // packed {src, wn-bits}
__device__ __align__(16) float g_W12[64 * 64];
__device__ __align__(16) float g_bv[64];
__device__ __align__(16) float g_W123[64 * 32];
__device__ __align__(16) float g_cvec[32];
__device__ __align__(16) float g_dvec[32];
__device__ __align__(16) float g_bufA[(size_t)NMAX * 64];
__device__ __align__(16) float g_bufB[(size_t)NMAX * 64];

template<int SEL>
__device__ __forceinline__ const float* sel_src(const float* p) {
    if (SEL == 1) return g_bufA;
    if (SEL == 2) return g_bufB;
    return p;
}
template<int SEL>
__device__ __forceinline__ float* sel_dst(float* p) {
    if (SEL == 1) return g_bufA;
    if (SEL == 2) return g_bufB;
    return p;
}

// ---------------- preprocessing --------------------------------------------
__global__ void init_nodes(int n) {
    int i = blockIdx.x * blockDim.x + threadIdx.x;
    if (i < n) { g_deg[i] = 1.0f; g_cnt[i] = 0; }
}

__global__ void edge_deg(const int* __restrict__ ei,
                         const float* __restrict__ ew, int E, int n) {
    int e = blockIdx.x * blockDim.x + threadIdx.x;
    if (e >= E) return;
    int c = ei[E + e];
    if ((unsigned)c >= (unsigned)n) return;   // guard
    atomicAdd(&g_deg[c], ew[e]);
    atomicAdd(&g_cnt[c], 1);
}

// scan of g_cnt -> g_off ; also computes dinv (fused, saves a launch)
__global__ void scan_blocks(int n) {
    __shared__ int s[SCAN_B];
    int t = threadIdx.x;
    int i = blockIdx.x * SCAN_B + t;
    if (i < n) g_dinv[i] = rsqrtf(g_deg[i]);
    int v = (i < n) ? g_cnt[i] : 0;
    s[t] = v;
    __syncthreads();
    for (int o = 1; o < SCAN_B; o <<= 1) {
        int x = (t >= o) ? s[t - o] : 0;
        __syncthreads();
        s[t] += x;
        __syncthreads();
    }
    if (i < n) g_off[i] = s[t] - v;
    if (t == SCAN_B - 1) g_bsum[blockIdx.x] = s[t];
}

__global__ void scan_sums(int nb) {
    __shared__ int s[128];
    int t = threadIdx.x;
    int v = (t < nb) ? g_bsum[t] : 0;
    s[t] = v;
    __syncthreads();
    for (int o = 1; o < 128; o <<= 1) {
        int x = (t >= o) ? s[t - o] : 0;
        __syncthreads();
        s[t] += x;
        __syncthreads();
    }
    if (t < nb) g_bpre[t] = s[t] - v;
}

__global__ void scan_add(int n) {
    int i = blockIdx.x * blockDim.x + threadIdx.x;
    if (i < n) {
        int o = g_off[i] + g_bpre[i >> 10];
        g_off[i] = o;
        g_cur[i] = o;
    }
}

__global__ void edge_scatter(const int* __restrict__ ei,
                             const float* __restrict__ ew, int E, int n) {
    int e = blockIdx.x * blockDim.x + threadIdx.x;
    if (e >= E) return;
    int r = ei[e];
    int c = ei[E + e];
    if ((unsigned)r >= (unsigned)n || (unsigned)c >= (unsigned)n) return;  // guard
    float wn = g_dinv[r] * ew[e] * g_dinv[c];
    int p = atomicAdd(&g_cur[c], 1);
    g_edge[p] = make_int2(r, __float_as_int(wn));
}

// ---------------- weight fusion --------------------------------------------
// stage 1: W12 = W1@W2 [64x64], bv = b1@W2 [64]
__global__ void fuse1(const float* __restrict__ W1, const float* __restrict__ W2,
                      const float* __restrict__ b1) {
    int t = blockIdx.x * 256 + threadIdx.x;
    if (t < 4096) {
        int i = t >> 6, j = t & 63;
        float s = 0.f;
#pragma unroll 8
        for (int k = 0; k < 128; k++) s += W1[i * 128 + k] * W2[k * 64 + j];
        g_W12[t] = s;
    } else if (t < 4096 + 64) {
        int j = t - 4096;
        float s = 0.f;
#pragma unroll 8
        for (int k = 0; k < 128; k++) s += b1[k] * W2[k * 64 + j];
        g_bv[j] = s;
    }
}

// stage 2: W123 = W12@W3 [64x32], c = bv@W3 [32], d = b2@W3 [32]
__global__ void fuse2(const float* __restrict__ W3, const float* __restrict__ b2) {
    int t = blockIdx.x * 256 + threadIdx.x;
    if (t < 2048) {
        int i = t >> 5, j = t & 31;
        float s = 0.f;
#pragma unroll 8
        for (int k = 0; k < 64; k++) s += g_W12[i * 64 + k] * W3[k * 32 + j];
        g_W123[t] = s;
    } else if (t < 2048 + 32) {
        int j = t - 2048;
        float s = 0.f;
#pragma unroll 8
        for (int k = 0; k < 64; k++) s += g_bv[k] * W3[k * 32 + j];
        g_cvec[j] = s;
    } else if (t < 2048 + 64) {
        int j = t - 2080;
        float s = 0.f;
#pragma unroll 8
        for (int k = 0; k < 64; k++) s += b2[k] * W3[k * 32 + j];
        g_dvec[j] = s;
    }
}

// ---------------- gather ----------------------------------------------------
// out = A*T ; WAMODE: 0 none, 1 write g_a = row sums, 2 write g_a2 = A.g_a
// BMODE: 0 none, 3 final: + g_a2[n]*c[m] + g_a[n]*d[m] + b3[m]
template<int M, int SSEL, int DSEL, int BMODE, bool SIG, int WAMODE>
__global__ void __launch_bounds__(256)
gather4_kernel(const float* __restrict__ Tp,
               const float* __restrict__ bias,
               float* __restrict__ outp, int n) {
    constexpr int L = M / 4;
    const float4* T = (const float4*)sel_src<SSEL>(Tp);
    float4* out = (float4*)sel_dst<DSEL>(outp);
    int node = blockIdx.x * (256 / L) + threadIdx.y;
    if (node >= n) return;
    int m = threadIdx.x;
    int start = g_off[node];
    int cnt   = g_cnt[node];

    float ax = 0.f, ay = 0.f, az = 0.f, aw = 0.f;
    float scal = 0.f;                 // wsum (WAMODE 1) or a-gather (WAMODE 2)
    int i = 0;
    for (; i + 4 <= cnt; i += 4) {
        int2 e0 = g_edge[start + i];
        int2 e1 = g_edge[start + i + 1];
        int2 e2 = g_edge[start + i + 2];
        int2 e3 = g_edge[start + i + 3];
        float4 t0 = T[(size_t)e0.x * L + m];
        float4 t1 = T[(size_t)e1.x * L + m];
        float4 t2 = T[(size_t)e2.x * L + m];
        float4 t3 = T[(size_t)e3.x * L + m];
        float w0 = __int_as_float(e0.y), w1 = __int_as_float(e1.y);
        float w2 = __int_as_float(e2.y), w3 = __int_as_float(e3.y);
        if (WAMODE == 1) scal += (w0 + w1) + (w2 + w3);
        if (WAMODE == 2)
            scal += w0 * g_a[e0.x] + w1 * g_a[e1.x] + w2 * g_a[e2.x] + w3 * g_a[e3.x];
        ax += w0 * t0.x; ay += w0 * t0.y; az += w0 * t0.z; aw += w0 * t0.w;
        ax += w1 * t1.x; ay += w1 * t1.y; az += w1 * t1.z; aw += w1 * t1.w;
        ax += w2 * t2.x; ay += w2 * t2.y; az += w2 * t2.z; aw += w2 * t2.w;
        ax += w3 * t3.x; ay += w3 * t3.y; az += w3 * t3.z; aw += w3 * t3.w;
    }
    for (; i < cnt; i++) {
        int2 e0 = g_edge[start + i];
        float4 t0 = T[(size_t)e0.x * L + m];
        float w0 = __int_as_float(e0.y);
        if (WAMODE == 1) scal += w0;
        if (WAMODE == 2) scal += w0 * g_a[e0.x];
        ax += w0 * t0.x; ay += w0 * t0.y; az += w0 * t0.z; aw += w0 * t0.w;
    }
    float di = g_dinv[node];
    float ns = di * di;
    float4 ts = T[(size_t)node * L + m];
    ax += ns * ts.x; ay += ns * ts.y; az += ns * ts.z; aw += ns * ts.w;
    if (WAMODE == 1 && m == 0) g_a[node] = scal + ns;
    if (WAMODE == 2 && m == 0) g_a2[node] = scal + ns * g_a[node];
    if (BMODE == 3) {
        float an  = g_a[node];
        float an2 = g_a2[node];
        float4 cc = ((const float4*)g_cvec)[m];
        float4 dd = ((const float4*)g_dvec)[m];
        float4 bb = ((const float4*)bias)[m];
        ax += an2 * cc.x + an * dd.x + bb.x;
        ay += an2 * cc.y + an * dd.y + bb.y;
        az += an2 * cc.z + an * dd.z + bb.z;
        aw += an2 * cc.w + an * dd.w + bb.w;
    }
    if (SIG) {
        ax = 1.0f / (1.0f + __expf(-ax));
        ay = 1.0f / (1.0f + __expf(-ay));
        az = 1.0f / (1.0f + __expf(-az));
        aw = 1.0f / (1.0f + __expf(-aw));
    }
    out[(size_t)node * L + m] = make_float4(ax, ay, az, aw);
}

// ---------------- GEMM (two-stage, R5 form): out[N,32] = A[N,64] @ W123 ----
__global__ void __launch_bounds__(64)
gemm_kernel(int n) {
    constexpr int K = 64, M = 32, BR = 64, KC = 32;
    constexpr int TX = M / 4, TY = 8;            // 8 x 8 = 64 threads
    const float* A = g_bufA;
    float* out = g_bufB;
    __shared__ float sW[K * M];
    __shared__ float sA[BR * KC];
    int tx = threadIdx.x, ty = threadIdx.y;
    int tid = ty * TX + tx;
    constexpr int NTH = TX * TY;
    for (int i = tid; i < K * M; i += NTH) sW[i] = g_W123[i];

    int row0 = blockIdx.x * BR;
    float acc[8][4];
#pragma unroll
    for (int r = 0; r < 8; r++)
#pragma unroll
        for (int c = 0; c < 4; c++) acc[r][c] = 0.0f;

    for (int kc = 0; kc < K; kc += KC) {
        __syncthreads();
        for (int i = tid; i < BR * KC; i += NTH) {
            int r = i / KC, k = i % KC;
            int gr = row0 + r;
            sA[i] = (gr < n) ? A[(size_t)gr * K + kc + k] : 0.0f;
        }
        __syncthreads();
#pragma unroll
        for (int k = 0; k < KC; k++) {
            float4 b4 = *(const float4*)&sW[(kc + k) * M + tx * 4];
#pragma unroll
            for (int r = 0; r < 8; r++) {
                float a = sA[(ty * 8 + r) * KC + k];
                acc[r][0] += a * b4.x;
                acc[r][1] += a * b4.y;
                acc[r][2] += a * b4.z;
                acc[r][3] += a * b4.w;
            }
        }
    }

#pragma unroll
    for (int r = 0; r < 8; r++) {
        int gr = row0 + ty * 8 + r;
        if (gr < n) {
            float4 v = make_float4(acc[r][0], acc[r][1], acc[r][2], acc[r][3]);
            *(float4*)&out[(size_t)gr * M + tx * 4] = v;
        }
    }
}

// ---------------- launch ----------------------------------------------------
extern "C" void kernel_launch(void* const* d_in, const int* in_sizes, int n_in,
                              void* d_out, int out_size) {
    const float* x  = (const float*)d_in[0];
    const int*   ei = (const int*)d_in[1];
    const float* ew = (const float*)d_in[2];
    const float* W1 = (const float*)d_in[3];
    const float* b1 = (const float*)d_in[4];
    const float* W2 = (const float*)d_in[5];
    const float* b2 = (const float*)d_in[6];
    const float* W3 = (const float*)d_in[7];
    const float* b3 = (const float*)d_in[8];
    float* out = (float*)d_out;

    int N = in_sizes[0] / 64;
    int E = in_sizes[1] / 2;

    int nb256_n = (N + 255) / 256;
    int nb256_e = (E + 255) / 256;
    int nbscan  = (N + SCAN_B - 1) / SCAN_B;

    // preprocessing + weight fusion (weight kernels overlap edge preprocessing)
    init_nodes<<<nb256_n, 256>>>(N);
    fuse1<<<17, 256>>>(W1, W2, b1);
    fuse2<<<9, 256>>>(W3, b2);
    edge_deg<<<nb256_e, 256>>>(ei, ew, E, N);
    scan_blocks<<<nbscan, SCAN_B>>>(N);
    scan_sums<<<1, 128>>>(nbscan);
    scan_add<<<nb256_n, 256>>>(N);
    edge_scatter<<<nb256_e, 256>>>(ei, ew, E, N);

    // G = A x -> bufA (writes g_a)
    gather4_kernel<64, 0, 1, 0, false, 1><<<(N + 15) / 16, dim3(16, 16)>>>(x, nullptr, nullptr, N);
    // V = G @ W123 -> bufB
    gemm_kernel<<<(N + 63) / 64, dim3(8, 8)>>>(N);
    // P = A V -> bufA (writes g_a2 = A.g_a)
    gather4_kernel<32, 2, 1, 0, false, 2><<<(N + 31) / 32, dim3(8, 32)>>>(nullptr, nullptr, nullptr, N);
    // out = sigmoid(A P + a2*c + a*d + b3)
    gather4_kernel<32, 1, 0, 3, true, 0><<<(N + 31) / 32, dim3(8, 32)>>>(nullptr, b3, out, N);

    (void)n_in; (void)out_size;
}